// round 2
// baseline (speedup 1.0000x reference)
#include <cuda_runtime.h>

// Problem constants (fixed-shape problem: logits [8,19,512,512] f32, target [8,512,512] int)
#define NCLS 19
#define HW   262144           // 512*512
#define CHW  (NCLS * HW)

// Global scratch (allocation-free rule: __device__ globals)
__device__ float g_ps[NCLS];     // per-class sum of probs
__device__ float g_inter[NCLS];  // per-class sum of p_t over pixels of that class
__device__ float g_cnt[NCLS];    // per-class pixel count
__device__ float g_scal[3];      // [0]=sum w_t, [1]=sum w_t*(-log_pt), [2]=sum focal terms

__global__ void fdl_zero_kernel() {
    int i = threadIdx.x;
    if (i < NCLS) { g_ps[i] = 0.f; g_inter[i] = 0.f; g_cnt[i] = 0.f; }
    if (i < 3)    { g_scal[i] = 0.f; }
}

__global__ void __launch_bounds__(256)
fdl_main_kernel(const float* __restrict__ logits,
                const int* __restrict__ target,     // harness materializes int64 as int32
                const float* __restrict__ cw,
                const float* __restrict__ fa,
                int P)
{
    __shared__ float s_cw[NCLS], s_fa[NCLS];
    __shared__ float s_ps[NCLS], s_inter[NCLS], s_cnt[NCLS];
    __shared__ float s_scal[3];

    const int tid = threadIdx.x;
    if (tid < NCLS) {
        s_cw[tid] = cw[tid];
        s_fa[tid] = fa[tid];
        s_ps[tid] = 0.f; s_inter[tid] = 0.f; s_cnt[tid] = 0.f;
    }
    if (tid < 3) s_scal[tid] = 0.f;
    __syncthreads();

    float ps[NCLS];
#pragma unroll
    for (int c = 0; c < NCLS; ++c) ps[c] = 0.f;
    float acc_w = 0.f, acc_wnll = 0.f, acc_focal = 0.f;

    const int stride = gridDim.x * blockDim.x;
    for (int pix = blockIdx.x * blockDim.x + tid; pix < P; pix += stride) {
        const int b  = pix / HW;          // constant power-of-2 -> shift
        const int hw = pix & (HW - 1);
        const float* base = logits + (long)b * CHW + hw;
        const int t = target[pix];

        // Pass 1: load all 19 class logits (19 coalesced streams) + running max
        float l[NCLS];
        float m = -3.402823466e38f;
#pragma unroll
        for (int c = 0; c < NCLS; ++c) {
            l[c] = __ldg(base + (long)c * HW);
            m = fmaxf(m, l[c]);
        }

        // Gather l[t] via predicated selects (no dynamic register indexing)
        float lt = l[0];
#pragma unroll
        for (int c = 1; c < NCLS; ++c) lt = (c == t) ? l[c] : lt;

        // Pass 2: exp + sum, overwrite l[] with exp values
        float S = 0.f;
#pragma unroll
        for (int c = 0; c < NCLS; ++c) {
            float e = __expf(l[c] - m);
            S += e;
            l[c] = e;
        }
        const float invS   = __frcp_rn(S);
        const float log_pt = (lt - m) - __logf(S);
        const float pt     = __expf(log_pt);            // equals exp(log_probs[t])

        const float wt = s_cw[t];
        const float at = s_fa[t];
        acc_w    += wt;
        acc_wnll -= wt * log_pt;
        const float ptf = fmaxf(pt, 1e-8f);
        const float om  = 1.f - ptf;
        acc_focal -= at * om * om * log_pt;

        atomicAdd(&s_inter[t], pt);
        atomicAdd(&s_cnt[t], 1.f);

#pragma unroll
        for (int c = 0; c < NCLS; ++c) ps[c] = fmaf(l[c], invS, ps[c]);
    }

    // Block reduction: warp shuffle, then smem atomics, then global atomics.
    const unsigned full = 0xffffffffu;
#pragma unroll
    for (int c = 0; c < NCLS; ++c) {
        float v = ps[c];
#pragma unroll
        for (int o = 16; o > 0; o >>= 1) v += __shfl_down_sync(full, v, o);
        if ((tid & 31) == 0) atomicAdd(&s_ps[c], v);
    }
    {
        float v0 = acc_w, v1 = acc_wnll, v2 = acc_focal;
#pragma unroll
        for (int o = 16; o > 0; o >>= 1) {
            v0 += __shfl_down_sync(full, v0, o);
            v1 += __shfl_down_sync(full, v1, o);
            v2 += __shfl_down_sync(full, v2, o);
        }
        if ((tid & 31) == 0) {
            atomicAdd(&s_scal[0], v0);
            atomicAdd(&s_scal[1], v1);
            atomicAdd(&s_scal[2], v2);
        }
    }
    __syncthreads();

    if (tid < NCLS) {
        atomicAdd(&g_ps[tid],    s_ps[tid]);
        atomicAdd(&g_inter[tid], s_inter[tid]);
        atomicAdd(&g_cnt[tid],   s_cnt[tid]);
    }
    if (tid >= 32 && tid < 35) atomicAdd(&g_scal[tid - 32], s_scal[tid - 32]);
}

__global__ void fdl_final_kernel(const float* __restrict__ cw,
                                 float* __restrict__ out, float Pf)
{
    if (threadIdx.x == 0) {
        const float ce    = g_scal[1] / g_scal[0];
        const float focal = g_scal[2] / Pf;

        float sw = 0.f;
#pragma unroll
        for (int c = 0; c < NCLS; ++c) sw += cw[c];
        sw = fmaxf(sw, 1e-8f);

        float dsum = 0.f;
#pragma unroll
        for (int c = 0; c < NCLS; ++c) {
            const float dice = (2.f * g_inter[c] + 1.f) / (g_ps[c] + g_cnt[c] + 1.f);
            dsum += dice * (cw[c] / sw);
        }
        const float dice_loss = 1.f - dsum;
        out[0] = 0.4f * ce + 0.3f * focal + 0.3f * dice_loss;
    }
}

extern "C" void kernel_launch(void* const* d_in, const int* in_sizes, int n_in,
                              void* d_out, int out_size)
{
    const float* logits = (const float*)d_in[0];
    const int*   target = (const int*)d_in[1];
    const float* cw     = (const float*)d_in[2];
    const float* fa     = (const float*)d_in[3];
    float*       out    = (float*)d_out;

    const int P = in_sizes[1];   // B*H*W = 2,097,152

    fdl_zero_kernel<<<1, 32>>>();
    fdl_main_kernel<<<1024, 256>>>(logits, target, cw, fa, P);
    fdl_final_kernel<<<1, 32>>>(cw, out, (float)P);
}